// round 14
// baseline (speedup 1.0000x reference)
#include <cuda_runtime.h>
#include <math.h>

// Problem constants
#define N_ITEMS 100001
#define DD      128
#define PP      3
#define SS      100
#define BB      256
#define TD      384          // 3*D
#define TAU_    0.1f
#define EPS_    0.01f

// ---------------- device scratch (no cudaMalloc allowed) ----------------
__device__ __align__(16) float  d_attr[PP * DD];          // normalized purpose rows
__device__ __align__(16) float4 d_gni[N_ITEMS];           // (g0,g1,g2, inv_norm)
__device__ __align__(16) float  d_GX[(size_t)SS * PP * BB * TD]; // 118 MB precomputed x-gates
__device__ __align__(16) float  d_HL[BB * TD];            // h_last, [b][p*128+d]

__device__ __forceinline__ float sigm(float x) { return 1.f / (1.f + expf(-x)); }

// ---------------- K0: normalize purpose_table (1 block, 128 thr) ----------------
__global__ void k0_attr(const float* __restrict__ pt) {
    int d = threadIdx.x;
    __shared__ float red[4];
    for (int p = 0; p < PP; p++) {
        float v = pt[p * DD + d];
        float ss = v * v;
        #pragma unroll
        for (int o = 16; o > 0; o >>= 1) ss += __shfl_xor_sync(0xffffffffu, ss, o);
        if ((d & 31) == 0) red[d >> 5] = ss;
        __syncthreads();
        float tot = red[0] + red[1] + red[2] + red[3];
        d_attr[p * DD + d] = v / fmaxf(sqrtf(tot), 1e-12f);
        __syncthreads();
    }
}

// ---------------- K1: per-item inv-norm + softmax gates (warp per item) ----------------
__global__ void __launch_bounds__(256) k1_gni(const float* __restrict__ emb) {
    __shared__ __align__(16) float attr_s[PP * DD];
    int tid = threadIdx.x;
    for (int i = tid; i < PP * DD; i += 256) attr_s[i] = d_attr[i];
    __syncthreads();

    int warp = tid >> 5, lane = tid & 31;
    int item = blockIdx.x * 8 + warp;
    if (item >= N_ITEMS) return;

    const float4* e4 = (const float4*)emb;
    const float4* a4 = (const float4*)attr_s;
    float4 v = e4[(size_t)item * 32 + lane];
    float ss = v.x * v.x + v.y * v.y + v.z * v.z + v.w * v.w;
    float4 a;
    a = a4[0 * 32 + lane]; float dp0 = v.x * a.x + v.y * a.y + v.z * a.z + v.w * a.w;
    a = a4[1 * 32 + lane]; float dp1 = v.x * a.x + v.y * a.y + v.z * a.z + v.w * a.w;
    a = a4[2 * 32 + lane]; float dp2 = v.x * a.x + v.y * a.y + v.z * a.z + v.w * a.w;
    #pragma unroll
    for (int o = 16; o > 0; o >>= 1) {
        ss  += __shfl_xor_sync(0xffffffffu, ss, o);
        dp0 += __shfl_xor_sync(0xffffffffu, dp0, o);
        dp1 += __shfl_xor_sync(0xffffffffu, dp1, o);
        dp2 += __shfl_xor_sync(0xffffffffu, dp2, o);
    }
    if (lane == 0) {
        float inv = 1.f / fmaxf(sqrtf(ss), 1e-12f);
        float s = inv * (1.f / TAU_);
        float l0 = dp0 * s, l1 = dp1 * s, l2 = dp2 * s;
        float m = fmaxf(l0, fmaxf(l1, l2));
        float e0 = expf(l0 - m), e1 = expf(l1 - m), e2 = expf(l2 - m);
        float r = 1.f / (e0 + e1 + e2);
        float g0 = e0 * r, g1 = e1 * r, g2 = e2 * r;
        if (item == 0) { g0 = g1 = g2 = 0.f; }   // g.at[0].set(0)
        d_gni[item] = make_float4(g0, g1, g2, inv);
    }
}

// ---------------- K2: GX[t,p,b,:] = emb[seq[t,b]] @ x2h_w[p]^T  (SGEMM 25600x384x128) ----
__global__ void __launch_bounds__(256) k2_gx(const int* __restrict__ seq,
                                             const float* __restrict__ emb,
                                             const float* __restrict__ x2h) {
    __shared__ __align__(16) float As[16 * 128];
    __shared__ __align__(16) float Bs[16 * 128];
    __shared__ int items[128];
    int tid = threadIdx.x;
    int row0 = blockIdx.x * 128;          // (t,b) rows
    int j0   = blockIdx.y * 128;          // output gate columns
    int p    = blockIdx.z;
    if (tid < 128) items[tid] = seq[row0 + tid];
    __syncthreads();

    const float4* E4 = (const float4*)emb;
    const float4* W4 = (const float4*)(x2h + (size_t)p * TD * DD);
    int tx = tid & 15, ty = tid >> 4;
    float acc[8][8];
    #pragma unroll
    for (int u = 0; u < 8; u++)
        #pragma unroll
        for (int v = 0; v < 8; v++) acc[u][v] = 0.f;

    for (int kc = 0; kc < DD; kc += 16) {
        #pragma unroll
        for (int q = 0; q < 2; q++) {
            int idx = (tid << 1) + q;
            int r = idx >> 2, k4 = idx & 3;
            float4 f = E4[(size_t)items[r] * 32 + (kc >> 2) + k4];
            As[(k4 * 4 + 0) * 128 + r] = f.x;
            As[(k4 * 4 + 1) * 128 + r] = f.y;
            As[(k4 * 4 + 2) * 128 + r] = f.z;
            As[(k4 * 4 + 3) * 128 + r] = f.w;
            float4 g = W4[(size_t)(j0 + r) * 32 + (kc >> 2) + k4];
            Bs[(k4 * 4 + 0) * 128 + r] = g.x;
            Bs[(k4 * 4 + 1) * 128 + r] = g.y;
            Bs[(k4 * 4 + 2) * 128 + r] = g.z;
            Bs[(k4 * 4 + 3) * 128 + r] = g.w;
        }
        __syncthreads();
        #pragma unroll
        for (int k = 0; k < 16; k++) {
            const float4* A4 = (const float4*)(As + k * 128);
            const float4* B4 = (const float4*)(Bs + k * 128);
            float4 a0 = A4[ty * 2], a1 = A4[ty * 2 + 1];
            float4 b0 = B4[tx * 2], b1 = B4[tx * 2 + 1];
            float ra[8] = {a0.x, a0.y, a0.z, a0.w, a1.x, a1.y, a1.z, a1.w};
            float rb[8] = {b0.x, b0.y, b0.z, b0.w, b1.x, b1.y, b1.z, b1.w};
            #pragma unroll
            for (int u = 0; u < 8; u++)
                #pragma unroll
                for (int v = 0; v < 8; v++) acc[u][v] = fmaf(ra[u], rb[v], acc[u][v]);
        }
        __syncthreads();
    }
    #pragma unroll
    for (int u = 0; u < 8; u++) {
        int rg = row0 + ty * 8 + u;
        int t = rg >> 8, b = rg & 255;
        size_t base = ((size_t)((t * 3 + p) * 256 + b)) * TD + j0 + tx * 8;
        float4* O = (float4*)(d_GX + base);
        O[0] = make_float4(acc[u][0], acc[u][1], acc[u][2], acc[u][3]);
        O[1] = make_float4(acc[u][4], acc[u][5], acc[u][6], acc[u][7]);
    }
}

// ---------------- K_scan: persistent per-chain PSRU scan -------------------------
// grid (43, 3): blockIdx.y = p, blockIdx.x covers 6 batch chains; Wh_p cached in smem.
#define SCAN_CH 6
__global__ void __launch_bounds__(384) k_scan(const int* __restrict__ seq,
                                              const int* __restrict__ lens,
                                              const float* __restrict__ h2h) {
    extern __shared__ __align__(16) float sm[];
    float* wt  = sm;                      // 49152 floats: Wh transposed [k4][j] as float4
    float* hs  = sm + 49152;              // 6*128 h state
    float* ghs = sm + 49152 + 768;        // 6*384 gh
    __shared__ int sl[SCAN_CH];
    __shared__ int smax;

    int tid = threadIdx.x;
    int p   = blockIdx.y;
    int b0  = blockIdx.x * SCAN_CH;
    int nch = min(SCAN_CH, BB - b0);

    const float4* W4 = (const float4*)(h2h + (size_t)p * TD * DD);
    float4* wt4 = (float4*)wt;
    #pragma unroll 4
    for (int k4 = 0; k4 < 32; k4++) wt4[k4 * 384 + tid] = W4[(size_t)tid * 32 + k4];
    for (int i = tid; i < SCAN_CH * 128; i += 384) hs[i] = 0.f;
    if (tid == 0) {
        int mx = 0;
        for (int c = 0; c < SCAN_CH; c++) {
            int L = (c < nch) ? lens[b0 + c] : 0;
            sl[c] = L;
            if (L > mx) mx = L;
        }
        smax = mx;
    }
    __syncthreads();
    int maxlen = smax;
    const float4* h4 = (const float4*)hs;

    for (int t = 0; t < maxlen; t++) {
        // phase 1: gh[c][j] = Wh row j . h[c]  (thread = j, all 6 chains)
        {
            float a0 = 0, a1 = 0, a2 = 0, a3 = 0, a4 = 0, a5 = 0;
            #pragma unroll 8
            for (int k4 = 0; k4 < 32; k4++) {
                float4 w = wt4[k4 * 384 + tid];
                float4 h;
                h = h4[0 * 32 + k4]; a0 = fmaf(w.x, h.x, a0); a0 = fmaf(w.y, h.y, a0); a0 = fmaf(w.z, h.z, a0); a0 = fmaf(w.w, h.w, a0);
                h = h4[1 * 32 + k4]; a1 = fmaf(w.x, h.x, a1); a1 = fmaf(w.y, h.y, a1); a1 = fmaf(w.z, h.z, a1); a1 = fmaf(w.w, h.w, a1);
                h = h4[2 * 32 + k4]; a2 = fmaf(w.x, h.x, a2); a2 = fmaf(w.y, h.y, a2); a2 = fmaf(w.z, h.z, a2); a2 = fmaf(w.w, h.w, a2);
                h = h4[3 * 32 + k4]; a3 = fmaf(w.x, h.x, a3); a3 = fmaf(w.y, h.y, a3); a3 = fmaf(w.z, h.z, a3); a3 = fmaf(w.w, h.w, a3);
                h = h4[4 * 32 + k4]; a4 = fmaf(w.x, h.x, a4); a4 = fmaf(w.y, h.y, a4); a4 = fmaf(w.z, h.z, a4); a4 = fmaf(w.w, h.w, a4);
                h = h4[5 * 32 + k4]; a5 = fmaf(w.x, h.x, a5); a5 = fmaf(w.y, h.y, a5); a5 = fmaf(w.z, h.z, a5); a5 = fmaf(w.w, h.w, a5);
            }
            ghs[0 * 384 + tid] = a0; ghs[1 * 384 + tid] = a1; ghs[2 * 384 + tid] = a2;
            ghs[3 * 384 + tid] = a3; ghs[4 * 384 + tid] = a4; ghs[5 * 384 + tid] = a5;
        }
        __syncthreads();
        // phase 2: PSRU cell update, 6 chains * 128 dims over 2 passes
        #pragma unroll
        for (int pass = 0; pass < 2; pass++) {
            int c = pass * 3 + (tid >> 7);
            int d = tid & 127;
            int L = sl[c];
            if (c < nch && t < L) {
                int b = b0 + c;
                int item = seq[t * BB + b];
                float4 gn = d_gni[item];
                float conc = (p == 0) ? gn.x : ((p == 1) ? gn.y : gn.z);
                size_t gxb = ((size_t)(t * 3 + p) * BB + b) * TD;
                float ir = d_GX[gxb + d];
                float ii = d_GX[gxb + 128 + d];
                float in_ = d_GX[gxb + 256 + d];
                float hr = ghs[c * 384 + d];
                float hi = ghs[c * 384 + 128 + d];
                float hn = ghs[c * 384 + 256 + d];
                float rg = sigm(ir + hr);
                float ig = sigm(ii + hi);
                float ng = tanhf(fmaf(rg, hn, in_));
                float mlt = (conc >= EPS_ ? conc : 0.f) * ig;
                float ho = hs[c * 128 + d];
                float hnew = fmaf(mlt, ng - ho, ho);
                hs[c * 128 + d] = hnew;
                if (t == L - 1) d_HL[(size_t)b * TD + p * DD + d] = hnew;
            }
        }
        __syncthreads();
    }
}

// ---------------- K3: out[b,i] = sigmoid( HL[b,:] . (g[i,p]*inv[i]*emb[i,d]) ) --------
__global__ void __launch_bounds__(256) k3_out(const float* __restrict__ emb,
                                              float* __restrict__ out) {
    __shared__ __align__(16) float As[16 * 128];
    __shared__ __align__(16) float Bs[16 * 128];
    int tid = threadIdx.x;
    int i0 = blockIdx.x * 128;            // item tile
    int b0 = blockIdx.y * 128;            // batch tile
    int tx = tid & 15, ty = tid >> 4;
    const float4* H4 = (const float4*)d_HL;
    const float4* E4 = (const float4*)emb;
    float acc[8][8];
    #pragma unroll
    for (int u = 0; u < 8; u++)
        #pragma unroll
        for (int v = 0; v < 8; v++) acc[u][v] = 0.f;

    for (int kc = 0; kc < TD; kc += 16) {
        int pp = kc >> 7;                 // purpose index of this k-chunk
        int d0 = kc & 127;
        #pragma unroll
        for (int q = 0; q < 2; q++) {
            int idx = (tid << 1) + q;
            int r = idx >> 2, k4 = idx & 3;
            float4 f = H4[(size_t)(b0 + r) * 96 + (kc >> 2) + k4];
            As[(k4 * 4 + 0) * 128 + r] = f.x;
            As[(k4 * 4 + 1) * 128 + r] = f.y;
            As[(k4 * 4 + 2) * 128 + r] = f.z;
            As[(k4 * 4 + 3) * 128 + r] = f.w;
            int it = i0 + r;
            float4 g = make_float4(0.f, 0.f, 0.f, 0.f);
            float gs = 0.f;
            if (it < N_ITEMS) {
                float4 gn = d_gni[it];
                float gp = (pp == 0) ? gn.x : ((pp == 1) ? gn.y : gn.z);
                gs = gp * gn.w;
                g = E4[(size_t)it * 32 + (d0 >> 2) + k4];
            }
            Bs[(k4 * 4 + 0) * 128 + r] = g.x * gs;
            Bs[(k4 * 4 + 1) * 128 + r] = g.y * gs;
            Bs[(k4 * 4 + 2) * 128 + r] = g.z * gs;
            Bs[(k4 * 4 + 3) * 128 + r] = g.w * gs;
        }
        __syncthreads();
        #pragma unroll
        for (int k = 0; k < 16; k++) {
            const float4* A4 = (const float4*)(As + k * 128);
            const float4* B4 = (const float4*)(Bs + k * 128);
            float4 a0 = A4[ty * 2], a1 = A4[ty * 2 + 1];
            float4 b0v = B4[tx * 2], b1v = B4[tx * 2 + 1];
            float ra[8] = {a0.x, a0.y, a0.z, a0.w, a1.x, a1.y, a1.z, a1.w};
            float rb[8] = {b0v.x, b0v.y, b0v.z, b0v.w, b1v.x, b1v.y, b1v.z, b1v.w};
            #pragma unroll
            for (int u = 0; u < 8; u++)
                #pragma unroll
                for (int v = 0; v < 8; v++) acc[u][v] = fmaf(ra[u], rb[v], acc[u][v]);
        }
        __syncthreads();
    }
    #pragma unroll
    for (int u = 0; u < 8; u++) {
        int b = b0 + ty * 8 + u;
        size_t ob = (size_t)b * N_ITEMS + i0 + tx * 8;
        #pragma unroll
        for (int v = 0; v < 8; v++) {
            int it = i0 + tx * 8 + v;
            if (it < N_ITEMS) out[ob + v] = sigm(acc[u][v]);
        }
    }
}

// ---------------- launch ----------------
extern "C" void kernel_launch(void* const* d_in, const int* in_sizes, int n_in,
                              void* d_out, int out_size) {
    const int*   seq  = (const int*)d_in[0];
    const int*   lens = (const int*)d_in[1];
    const float* emb  = (const float*)d_in[2];
    const float* pt   = (const float*)d_in[3];
    const float* x2h  = (const float*)d_in[4];
    const float* h2h  = (const float*)d_in[5];
    float* out = (float*)d_out;

    k0_attr<<<1, 128>>>(pt);
    k1_gni<<<(N_ITEMS + 7) / 8, 256>>>(emb);
    k2_gx<<<dim3(SS * BB / 128, TD / 128, PP), 256>>>(seq, emb, x2h);

    const size_t scan_smem = (49152 + 768 + 2304) * sizeof(float);  // 208896 B
    cudaFuncSetAttribute(k_scan, cudaFuncAttributeMaxDynamicSharedMemorySize,
                         (int)scan_smem);
    k_scan<<<dim3((BB + SCAN_CH - 1) / SCAN_CH, PP), 384, scan_smem>>>(seq, lens, h2h);

    k3_out<<<dim3((N_ITEMS + 127) / 128, BB / 128), 256>>>(emb, out);
}

// round 15
// speedup vs baseline: 1.0052x; 1.0052x over previous
#include <cuda_runtime.h>
#include <math.h>

// Problem constants
#define N_ITEMS 100001
#define DD      128
#define PP      3
#define SS      100
#define BB      256
#define TD      384          // 3*D
#define TAU_    0.1f
#define EPS_    0.01f

// ---------------- device scratch (no cudaMalloc allowed) ----------------
__device__ __align__(16) float  d_attr[PP * DD];          // normalized purpose rows
__device__ __align__(16) float4 d_gni[N_ITEMS];           // (g0,g1,g2, inv_norm)
__device__ __align__(16) float  d_GX[(size_t)SS * PP * BB * TD]; // 118 MB precomputed x-gates
__device__ __align__(16) float  d_HL[BB * TD];            // h_last, [b][p*128+d]

__device__ __forceinline__ float sigm(float x) { return 1.f / (1.f + expf(-x)); }

// ---- packed fp32 (sm_100+): one FFMA-pipe slot = 2 MACs ----
__device__ __forceinline__ void fma2(unsigned long long& d,
                                     unsigned long long a,
                                     unsigned long long b) {
    asm("fma.rn.f32x2 %0, %1, %2, %0;" : "+l"(d) : "l"(a), "l"(b));
}
__device__ __forceinline__ unsigned long long pack2(float lo, float hi) {
    unsigned long long r;
    asm("mov.b64 %0, {%1, %2};" : "=l"(r) : "f"(lo), "f"(hi));
    return r;
}
__device__ __forceinline__ float2 unpack2(unsigned long long v) {
    float2 r;
    asm("mov.b64 {%0, %1}, %2;" : "=f"(r.x), "=f"(r.y) : "l"(v));
    return r;
}

// ---------------- K0: normalize purpose_table (1 block, 128 thr) ----------------
__global__ void k0_attr(const float* __restrict__ pt) {
    int d = threadIdx.x;
    __shared__ float red[4];
    for (int p = 0; p < PP; p++) {
        float v = pt[p * DD + d];
        float ss = v * v;
        #pragma unroll
        for (int o = 16; o > 0; o >>= 1) ss += __shfl_xor_sync(0xffffffffu, ss, o);
        if ((d & 31) == 0) red[d >> 5] = ss;
        __syncthreads();
        float tot = red[0] + red[1] + red[2] + red[3];
        d_attr[p * DD + d] = v / fmaxf(sqrtf(tot), 1e-12f);
        __syncthreads();
    }
}

// ---------------- K1: per-item inv-norm + softmax gates (warp per item) ----------------
__global__ void __launch_bounds__(256) k1_gni(const float* __restrict__ emb) {
    __shared__ __align__(16) float attr_s[PP * DD];
    int tid = threadIdx.x;
    for (int i = tid; i < PP * DD; i += 256) attr_s[i] = d_attr[i];
    __syncthreads();

    int warp = tid >> 5, lane = tid & 31;
    int item = blockIdx.x * 8 + warp;
    if (item >= N_ITEMS) return;

    const float4* e4 = (const float4*)emb;
    const float4* a4 = (const float4*)attr_s;
    float4 v = e4[(size_t)item * 32 + lane];
    float ss = v.x * v.x + v.y * v.y + v.z * v.z + v.w * v.w;
    float4 a;
    a = a4[0 * 32 + lane]; float dp0 = v.x * a.x + v.y * a.y + v.z * a.z + v.w * a.w;
    a = a4[1 * 32 + lane]; float dp1 = v.x * a.x + v.y * a.y + v.z * a.z + v.w * a.w;
    a = a4[2 * 32 + lane]; float dp2 = v.x * a.x + v.y * a.y + v.z * a.z + v.w * a.w;
    #pragma unroll
    for (int o = 16; o > 0; o >>= 1) {
        ss  += __shfl_xor_sync(0xffffffffu, ss, o);
        dp0 += __shfl_xor_sync(0xffffffffu, dp0, o);
        dp1 += __shfl_xor_sync(0xffffffffu, dp1, o);
        dp2 += __shfl_xor_sync(0xffffffffu, dp2, o);
    }
    if (lane == 0) {
        float inv = 1.f / fmaxf(sqrtf(ss), 1e-12f);
        float s = inv * (1.f / TAU_);
        float l0 = dp0 * s, l1 = dp1 * s, l2 = dp2 * s;
        float m = fmaxf(l0, fmaxf(l1, l2));
        float e0 = expf(l0 - m), e1 = expf(l1 - m), e2 = expf(l2 - m);
        float r = 1.f / (e0 + e1 + e2);
        float g0 = e0 * r, g1 = e1 * r, g2 = e2 * r;
        if (item == 0) { g0 = g1 = g2 = 0.f; }   // g.at[0].set(0)
        d_gni[item] = make_float4(g0, g1, g2, inv);
    }
}

// ---------------- K2: GX[t,p,b,:] = emb[seq[t,b]] @ x2h_w[p]^T  (SGEMM 25600x384x128) ----
__global__ void __launch_bounds__(256) k2_gx(const int* __restrict__ seq,
                                             const float* __restrict__ emb,
                                             const float* __restrict__ x2h) {
    __shared__ __align__(16) float As[16 * 128];
    __shared__ __align__(16) float Bs[16 * 128];
    __shared__ int items[128];
    int tid = threadIdx.x;
    int row0 = blockIdx.x * 128;          // (t,b) rows
    int j0   = blockIdx.y * 128;          // output gate columns
    int p    = blockIdx.z;
    if (tid < 128) items[tid] = seq[row0 + tid];
    __syncthreads();

    const float4* E4 = (const float4*)emb;
    const float4* W4 = (const float4*)(x2h + (size_t)p * TD * DD);
    int tx = tid & 15, ty = tid >> 4;
    unsigned long long acc2[8][4];
    #pragma unroll
    for (int u = 0; u < 8; u++)
        #pragma unroll
        for (int v = 0; v < 4; v++) acc2[u][v] = 0ull;

    for (int kc = 0; kc < DD; kc += 16) {
        #pragma unroll
        for (int q = 0; q < 2; q++) {
            int idx = (tid << 1) + q;
            int r = idx >> 2, k4 = idx & 3;
            float4 f = E4[(size_t)items[r] * 32 + (kc >> 2) + k4];
            As[(k4 * 4 + 0) * 128 + r] = f.x;
            As[(k4 * 4 + 1) * 128 + r] = f.y;
            As[(k4 * 4 + 2) * 128 + r] = f.z;
            As[(k4 * 4 + 3) * 128 + r] = f.w;
            float4 g = W4[(size_t)(j0 + r) * 32 + (kc >> 2) + k4];
            Bs[(k4 * 4 + 0) * 128 + r] = g.x;
            Bs[(k4 * 4 + 1) * 128 + r] = g.y;
            Bs[(k4 * 4 + 2) * 128 + r] = g.z;
            Bs[(k4 * 4 + 3) * 128 + r] = g.w;
        }
        __syncthreads();
        #pragma unroll
        for (int k = 0; k < 16; k++) {
            const float4* A4 = (const float4*)(As + k * 128);
            const float* Brow = Bs + k * 128;
            float4 a0 = A4[ty * 2], a1 = A4[ty * 2 + 1];
            ulonglong2 bp0 = *(const ulonglong2*)(Brow + tx * 8);
            ulonglong2 bp1 = *(const ulonglong2*)(Brow + tx * 8 + 4);
            unsigned long long rb0 = bp0.x, rb1 = bp0.y, rb2 = bp1.x, rb3 = bp1.y;
            float ra[8] = {a0.x, a0.y, a0.z, a0.w, a1.x, a1.y, a1.z, a1.w};
            #pragma unroll
            for (int u = 0; u < 8; u++) {
                unsigned long long ad = pack2(ra[u], ra[u]);
                fma2(acc2[u][0], ad, rb0);
                fma2(acc2[u][1], ad, rb1);
                fma2(acc2[u][2], ad, rb2);
                fma2(acc2[u][3], ad, rb3);
            }
        }
        __syncthreads();
    }
    #pragma unroll
    for (int u = 0; u < 8; u++) {
        int rg = row0 + ty * 8 + u;
        int t = rg >> 8, b = rg & 255;
        size_t base = ((size_t)((t * 3 + p) * 256 + b)) * TD + j0 + tx * 8;
        float4* O = (float4*)(d_GX + base);
        float2 f0 = unpack2(acc2[u][0]), f1 = unpack2(acc2[u][1]);
        float2 f2 = unpack2(acc2[u][2]), f3 = unpack2(acc2[u][3]);
        O[0] = make_float4(f0.x, f0.y, f1.x, f1.y);
        O[1] = make_float4(f2.x, f2.y, f3.x, f3.y);
    }
}

// ---------------- K_scan: persistent per-chain PSRU scan -------------------------
// grid (43, 3): blockIdx.y = p, blockIdx.x covers 6 batch chains; Wh_p cached in smem.
// h state stored chain-interleaved (hs_i[d*8 + c]) so the matvec loads chain-pairs
// as u64 broadcasts and uses fma.rn.f32x2 (2 MACs per FFMA-pipe slot).
// d_GX / seq / gni for step t+1 are prefetched into registers during step t.
#define SCAN_CH 6
__global__ void __launch_bounds__(384) k_scan(const int* __restrict__ seq,
                                              const int* __restrict__ lens,
                                              const float* __restrict__ h2h) {
    extern __shared__ __align__(16) float sm[];
    float* wt   = sm;                       // 49152 floats: Wh transposed [k4][j] as float4
    float* hs_i = sm + 49152;               // 128*8 floats: h state, [d][c] (2 pad slots)
    float* ghs  = sm + 49152 + 1024;        // 6*384 gh
    __shared__ int sl[SCAN_CH];
    __shared__ int smax;

    int tid = threadIdx.x;
    int p   = blockIdx.y;
    int b0  = blockIdx.x * SCAN_CH;
    int nch = min(SCAN_CH, BB - b0);

    const float4* W4 = (const float4*)(h2h + (size_t)p * TD * DD);
    float4* wt4 = (float4*)wt;
    #pragma unroll 4
    for (int k4 = 0; k4 < 32; k4++) wt4[k4 * 384 + tid] = W4[(size_t)tid * 32 + k4];
    for (int i = tid; i < 128 * 8; i += 384) hs_i[i] = 0.f;
    if (tid == 0) {
        int mx = 0;
        for (int c = 0; c < SCAN_CH; c++) {
            int L = (c < nch) ? lens[b0 + c] : 0;
            sl[c] = L;
            if (L > mx) mx = L;
        }
        smax = mx;
    }
    __syncthreads();
    int maxlen = smax;

    // prefetch registers (per phase-2 pass)
    float f_ir[2] = {0.f, 0.f}, f_ii[2] = {0.f, 0.f};
    float f_in[2] = {0.f, 0.f}, f_cc[2] = {0.f, 0.f};
    {
        #pragma unroll
        for (int pass = 0; pass < 2; pass++) {
            int c = pass * 3 + (tid >> 7);
            int d = tid & 127;
            if (c < nch && 0 < sl[c]) {
                int b = b0 + c;
                int item = seq[b];            // t = 0
                float4 gn = d_gni[item];
                f_cc[pass] = (p == 0) ? gn.x : ((p == 1) ? gn.y : gn.z);
                size_t gxb = ((size_t)p * BB + b) * TD;
                f_ir[pass] = d_GX[gxb + d];
                f_ii[pass] = d_GX[gxb + 128 + d];
                f_in[pass] = d_GX[gxb + 256 + d];
            }
        }
    }

    for (int t = 0; t < maxlen; t++) {
        // phase 1: gh[c][j] = Wh row j . h[c]  (thread = j; 3 packed chain-pair accs)
        {
            unsigned long long a01 = 0ull, a23 = 0ull, a45 = 0ull;
            #pragma unroll 4
            for (int k4 = 0; k4 < 32; k4++) {
                float4 w = wt4[k4 * 384 + tid];
                const float* hb = hs_i + k4 * 32;
                #pragma unroll
                for (int kk = 0; kk < 4; kk++) {
                    const float* hk = hb + kk * 8;
                    ulonglong2 h03 = *(const ulonglong2*)hk;                 // {c0c1, c2c3}
                    unsigned long long h45 = *(const unsigned long long*)(hk + 4);
                    float ws = (kk == 0) ? w.x : (kk == 1) ? w.y : (kk == 2) ? w.z : w.w;
                    unsigned long long wd = pack2(ws, ws);
                    fma2(a01, wd, h03.x);
                    fma2(a23, wd, h03.y);
                    fma2(a45, wd, h45);
                }
            }
            float2 r01 = unpack2(a01), r23 = unpack2(a23), r45 = unpack2(a45);
            ghs[0 * 384 + tid] = r01.x; ghs[1 * 384 + tid] = r01.y;
            ghs[2 * 384 + tid] = r23.x; ghs[3 * 384 + tid] = r23.y;
            ghs[4 * 384 + tid] = r45.x; ghs[5 * 384 + tid] = r45.y;
        }
        __syncthreads();
        // phase 2: PSRU cell update using prefetched x-gates
        #pragma unroll
        for (int pass = 0; pass < 2; pass++) {
            int c = pass * 3 + (tid >> 7);
            int d = tid & 127;
            int L = sl[c];
            if (c < nch && t < L) {
                float hr = ghs[c * 384 + d];
                float hi = ghs[c * 384 + 128 + d];
                float hn = ghs[c * 384 + 256 + d];
                float rg = sigm(f_ir[pass] + hr);
                float ig = sigm(f_ii[pass] + hi);
                float ng = tanhf(fmaf(rg, hn, f_in[pass]));
                float mlt = (f_cc[pass] >= EPS_ ? f_cc[pass] : 0.f) * ig;
                float ho = hs_i[d * 8 + c];
                float hnew = fmaf(mlt, ng - ho, ho);
                hs_i[d * 8 + c] = hnew;
                if (t == L - 1) d_HL[(size_t)(b0 + c) * TD + p * DD + d] = hnew;
            }
        }
        // prefetch step t+1 (overlaps next phase 1)
        if (t + 1 < maxlen) {
            #pragma unroll
            for (int pass = 0; pass < 2; pass++) {
                int c = pass * 3 + (tid >> 7);
                int d = tid & 127;
                if (c < nch && (t + 1) < sl[c]) {
                    int b = b0 + c;
                    int item = seq[(t + 1) * BB + b];
                    float4 gn = d_gni[item];
                    f_cc[pass] = (p == 0) ? gn.x : ((p == 1) ? gn.y : gn.z);
                    size_t gxb = ((size_t)((t + 1) * 3 + p) * BB + b) * TD;
                    f_ir[pass] = d_GX[gxb + d];
                    f_ii[pass] = d_GX[gxb + 128 + d];
                    f_in[pass] = d_GX[gxb + 256 + d];
                }
            }
        }
        __syncthreads();
    }
}

// ---------------- K3: out[b,i] = sigmoid( HL[b,:] . (g[i,p]*inv[i]*emb[i,d]) ) --------
__global__ void __launch_bounds__(256) k3_out(const float* __restrict__ emb,
                                              float* __restrict__ out) {
    __shared__ __align__(16) float As[16 * 128];
    __shared__ __align__(16) float Bs[16 * 128];
    int tid = threadIdx.x;
    int i0 = blockIdx.x * 128;            // item tile
    int b0 = blockIdx.y * 128;            // batch tile
    int tx = tid & 15, ty = tid >> 4;
    const float4* H4 = (const float4*)d_HL;
    const float4* E4 = (const float4*)emb;
    unsigned long long acc2[8][4];
    #pragma unroll
    for (int u = 0; u < 8; u++)
        #pragma unroll
        for (int v = 0; v < 4; v++) acc2[u][v] = 0ull;

    for (int kc = 0; kc < TD; kc += 16) {
        int pp = kc >> 7;                 // purpose index of this k-chunk
        int d0 = kc & 127;
        #pragma unroll
        for (int q = 0; q < 2; q++) {
            int idx = (tid << 1) + q;
            int r = idx >> 2, k4 = idx & 3;
            float4 f = H4[(size_t)(b0 + r) * 96 + (kc >> 2) + k4];
            As[(k4 * 4 + 0) * 128 + r] = f.x;
            As[(k4 * 4 + 1) * 128 + r] = f.y;
            As[(k4 * 4 + 2) * 128 + r] = f.z;
            As[(k4 * 4 + 3) * 128 + r] = f.w;
            int it = i0 + r;
            float4 g = make_float4(0.f, 0.f, 0.f, 0.f);
            float gs = 0.f;
            if (it < N_ITEMS) {
                float4 gn = d_gni[it];
                float gp = (pp == 0) ? gn.x : ((pp == 1) ? gn.y : gn.z);
                gs = gp * gn.w;
                g = E4[(size_t)it * 32 + (d0 >> 2) + k4];
            }
            Bs[(k4 * 4 + 0) * 128 + r] = g.x * gs;
            Bs[(k4 * 4 + 1) * 128 + r] = g.y * gs;
            Bs[(k4 * 4 + 2) * 128 + r] = g.z * gs;
            Bs[(k4 * 4 + 3) * 128 + r] = g.w * gs;
        }
        __syncthreads();
        #pragma unroll
        for (int k = 0; k < 16; k++) {
            const float4* A4 = (const float4*)(As + k * 128);
            const float* Brow = Bs + k * 128;
            float4 a0 = A4[ty * 2], a1 = A4[ty * 2 + 1];
            ulonglong2 bp0 = *(const ulonglong2*)(Brow + tx * 8);
            ulonglong2 bp1 = *(const ulonglong2*)(Brow + tx * 8 + 4);
            unsigned long long rb0 = bp0.x, rb1 = bp0.y, rb2 = bp1.x, rb3 = bp1.y;
            float ra[8] = {a0.x, a0.y, a0.z, a0.w, a1.x, a1.y, a1.z, a1.w};
            #pragma unroll
            for (int u = 0; u < 8; u++) {
                unsigned long long ad = pack2(ra[u], ra[u]);
                fma2(acc2[u][0], ad, rb0);
                fma2(acc2[u][1], ad, rb1);
                fma2(acc2[u][2], ad, rb2);
                fma2(acc2[u][3], ad, rb3);
            }
        }
        __syncthreads();
    }
    #pragma unroll
    for (int u = 0; u < 8; u++) {
        int b = b0 + ty * 8 + u;
        size_t ob = (size_t)b * N_ITEMS + i0 + tx * 8;
        #pragma unroll
        for (int v4 = 0; v4 < 4; v4++) {
            float2 f = unpack2(acc2[u][v4]);
            int it = i0 + tx * 8 + v4 * 2;
            if (it < N_ITEMS)     out[ob + v4 * 2]     = sigm(f.x);
            if (it + 1 < N_ITEMS) out[ob + v4 * 2 + 1] = sigm(f.y);
        }
    }
}

// ---------------- launch ----------------
extern "C" void kernel_launch(void* const* d_in, const int* in_sizes, int n_in,
                              void* d_out, int out_size) {
    const int*   seq  = (const int*)d_in[0];
    const int*   lens = (const int*)d_in[1];
    const float* emb  = (const float*)d_in[2];
    const float* pt   = (const float*)d_in[3];
    const float* x2h  = (const float*)d_in[4];
    const float* h2h  = (const float*)d_in[5];
    float* out = (float*)d_out;

    k0_attr<<<1, 128>>>(pt);
    k1_gni<<<(N_ITEMS + 7) / 8, 256>>>(emb);
    k2_gx<<<dim3(SS * BB / 128, TD / 128, PP), 256>>>(seq, emb, x2h);

    const size_t scan_smem = (49152 + 1024 + 2304) * sizeof(float);  // 209920 B
    cudaFuncSetAttribute(k_scan, cudaFuncAttributeMaxDynamicSharedMemorySize,
                         (int)scan_smem);
    k_scan<<<dim3((BB + SCAN_CH - 1) / SCAN_CH, PP), 384, scan_smem>>>(seq, lens, h2h);

    k3_out<<<dim3((N_ITEMS + 127) / 128, BB / 128), 256>>>(emb, out);
}